// round 1
// baseline (speedup 1.0000x reference)
#include <cuda_runtime.h>
#include <math.h>

// Problem constants
#define BB   2
#define SS   2048
#define DD   1024
#define HH   16
#define HDIM 64
#define DFFN 4096
#define ROWS (BB * SS)   // 4096

// -------- scratch (static device globals; no allocation) --------
__device__ float g_h[ROWS * DD];          // LN1(x) + pos_emb      (16 MB)
__device__ float g_qkv[ROWS * 3 * DD];    // qkv projections        (48 MB)
__device__ float g_attn[ROWS * DD];       // attention out [B,S,D]  (16 MB)
__device__ float g_x2[ROWS * DD];         // x + attn @ w_o + b_o   (16 MB)
__device__ float g_m[ROWS * DD];          // LN2(x2)                (16 MB)
__device__ float g_ff[ROWS * DFFN];       // gelu(m@w_fc + b_fc)    (64 MB)

// ---------------- GELU (tanh approximation, matches jax.nn.gelu default) ---
__device__ __forceinline__ float gelu_tanh(float x) {
    float x3 = x * x * x;
    float t = tanhf(0.7978845608028654f * (x + 0.044715f * x3));
    return 0.5f * x * (1.0f + t);
}

// ---------------- LayerNorm (+ optional pos_emb add) -----------------------
// one block per row, 256 threads, 4 floats/thread (D=1024)
__global__ void ln_kernel(const float* __restrict__ x,
                          const float* __restrict__ gam,
                          const float* __restrict__ bet,
                          const float* __restrict__ pos,   // nullptr => no add
                          float* __restrict__ out)
{
    int row = blockIdx.x;
    int tid = threadIdx.x;
    const float4* xr = (const float4*)(x + (size_t)row * DD);
    float4 v = xr[tid];
    float s  = v.x + v.y + v.z + v.w;
    float ss = v.x * v.x + v.y * v.y + v.z * v.z + v.w * v.w;
#pragma unroll
    for (int o = 16; o > 0; o >>= 1) {
        s  += __shfl_xor_sync(0xffffffffu, s,  o);
        ss += __shfl_xor_sync(0xffffffffu, ss, o);
    }
    __shared__ float sb[8], sb2[8], stats[2];
    int wid = tid >> 5, lane = tid & 31;
    if (lane == 0) { sb[wid] = s; sb2[wid] = ss; }
    __syncthreads();
    if (tid == 0) {
        float ts = 0.f, tss = 0.f;
#pragma unroll
        for (int i = 0; i < 8; i++) { ts += sb[i]; tss += sb2[i]; }
        float mu  = ts  * (1.0f / DD);
        float var = tss * (1.0f / DD) - mu * mu;
        stats[0] = mu;
        stats[1] = rsqrtf(var + 1e-5f);
    }
    __syncthreads();
    float mu = stats[0], rs = stats[1];
    int c = tid * 4;
    float4 gg = *(const float4*)(gam + c);
    float4 bb = *(const float4*)(bet + c);
    float4 o4;
    o4.x = (v.x - mu) * rs * gg.x + bb.x;
    o4.y = (v.y - mu) * rs * gg.y + bb.y;
    o4.z = (v.z - mu) * rs * gg.z + bb.z;
    o4.w = (v.w - mu) * rs * gg.w + bb.w;
    if (pos) {
        int srow = row % SS;
        float4 p = *(const float4*)(pos + (size_t)srow * DD + c);
        o4.x += p.x; o4.y += p.y; o4.z += p.z; o4.w += p.w;
    }
    ((float4*)(out + (size_t)row * DD))[tid] = o4;
}

// ---------------- Tiled fp32 GEMM: C = A[MxK] @ B[KxN] + epilogue ----------
// 128x128 tile, BK=16, 256 threads, 8x8 microtile per thread.
// EPI: 0 = +bias ; 1 = gelu(+bias) ; 2 = +bias + res
template <int EPI>
__global__ __launch_bounds__(256)
void gemm_kernel(const float* __restrict__ A, const float* __restrict__ Bm,
                 const float* __restrict__ bias, const float* __restrict__ res,
                 float* __restrict__ C, int M, int N, int K)
{
    __shared__ float As[16][128];
    __shared__ float Bs[16][128];
    int tid = threadIdx.x;
    int bn = blockIdx.x, bm = blockIdx.y;

    int aRow = tid >> 2;             // 0..63
    int aCol = (tid & 3) << 2;       // 0,4,8,12
    int bRow = tid >> 5;             // 0..7
    int bCol = (tid & 31) << 2;      // 0..124
    int tx = tid & 15, ty = tid >> 4;

    const float* Ap0 = A + (size_t)(bm * 128 + aRow) * K + aCol;
    const float* Ap1 = A + (size_t)(bm * 128 + aRow + 64) * K + aCol;
    const float* Bp0 = Bm + (size_t)bRow * N + bn * 128 + bCol;
    const float* Bp1 = Bm + (size_t)(bRow + 8) * N + bn * 128 + bCol;

    float acc[8][8];
#pragma unroll
    for (int i = 0; i < 8; i++)
#pragma unroll
        for (int j = 0; j < 8; j++) acc[i][j] = 0.f;

    for (int k0 = 0; k0 < K; k0 += 16) {
        float4 av0 = *(const float4*)(Ap0 + k0);
        float4 av1 = *(const float4*)(Ap1 + k0);
        float4 bv0 = *(const float4*)(Bp0 + (size_t)k0 * N);
        float4 bv1 = *(const float4*)(Bp1 + (size_t)k0 * N);
        __syncthreads();
        As[aCol + 0][aRow] = av0.x;
        As[aCol + 1][aRow] = av0.y;
        As[aCol + 2][aRow] = av0.z;
        As[aCol + 3][aRow] = av0.w;
        As[aCol + 0][aRow + 64] = av1.x;
        As[aCol + 1][aRow + 64] = av1.y;
        As[aCol + 2][aRow + 64] = av1.z;
        As[aCol + 3][aRow + 64] = av1.w;
        *(float4*)&Bs[bRow][bCol]     = bv0;
        *(float4*)&Bs[bRow + 8][bCol] = bv1;
        __syncthreads();
#pragma unroll
        for (int kk = 0; kk < 16; kk++) {
            float a[8], b[8];
            *(float4*)&a[0] = *(const float4*)&As[kk][ty * 8];
            *(float4*)&a[4] = *(const float4*)&As[kk][ty * 8 + 4];
            *(float4*)&b[0] = *(const float4*)&Bs[kk][tx * 8];
            *(float4*)&b[4] = *(const float4*)&Bs[kk][tx * 8 + 4];
#pragma unroll
            for (int i = 0; i < 8; i++)
#pragma unroll
                for (int j = 0; j < 8; j++) acc[i][j] += a[i] * b[j];
        }
    }

    int row0 = bm * 128 + ty * 8;
    int col0 = bn * 128 + tx * 8;
#pragma unroll
    for (int i = 0; i < 8; i++) {
        size_t base = (size_t)(row0 + i) * N + col0;
#pragma unroll
        for (int j = 0; j < 8; j++) {
            float v = acc[i][j] + bias[col0 + j];
            if (EPI == 1) v = gelu_tanh(v);
            if (EPI == 2) v += res[base + j];
            C[base + j] = v;
        }
    }
}

// ---------------- Causal attention (online softmax / flash style) ----------
// grid: (S/32, H, B), block: 128 threads.
// 32 queries per block; 4 threads per query, each owning 16 head dims.
__global__ __launch_bounds__(128)
void attn_kernel(const float* __restrict__ qkv, float* __restrict__ out)
{
    __shared__ float Ks[32][64];
    __shared__ float Vs[32][64];
    int qt = blockIdx.x, h = blockIdx.y, b = blockIdx.z;
    int tid = threadIdx.x;
    int ql = tid >> 2;       // 0..31 query within tile
    int cs = tid & 3;        // 0..3 dim-chunk
    int q0 = qt * 32;
    int qglob = q0 + ql;

    // load q fragment (16 floats) into registers, pre-scaled by 1/sqrt(64)
    size_t qbase = ((size_t)(b * SS + qglob) * 3 + 0) * DD + h * HDIM + cs * 16;
    float4 qv[4];
#pragma unroll
    for (int c = 0; c < 4; c++) {
        qv[c] = *(const float4*)(qkv + qbase + c * 4);
        qv[c].x *= 0.125f; qv[c].y *= 0.125f; qv[c].z *= 0.125f; qv[c].w *= 0.125f;
    }

    float4 acc4[4];
#pragma unroll
    for (int c = 0; c < 4; c++) acc4[c] = make_float4(0.f, 0.f, 0.f, 0.f);
    float mrun = -1e30f, l = 0.f;

    for (int kt = 0; kt <= qt; kt++) {
        __syncthreads();
        int sk = kt * 32 + ql;
        const float4* kg = (const float4*)(qkv + ((size_t)(b * SS + sk) * 3 + 1) * DD + h * HDIM + cs * 16);
        const float4* vg = (const float4*)(qkv + ((size_t)(b * SS + sk) * 3 + 2) * DD + h * HDIM + cs * 16);
        float4* kd = (float4*)&Ks[ql][cs * 16];
        float4* vd = (float4*)&Vs[ql][cs * 16];
#pragma unroll
        for (int c = 0; c < 4; c++) { kd[c] = kg[c]; vd[c] = vg[c]; }
        __syncthreads();

        float sc[32];
        float mt = -1e30f;
#pragma unroll
        for (int kc = 0; kc < 32; kc++) {
            const float4* kr = (const float4*)&Ks[kc][cs * 16];
            float p = 0.f;
#pragma unroll
            for (int c = 0; c < 4; c++) {
                float4 kk = kr[c];
                p += qv[c].x * kk.x + qv[c].y * kk.y + qv[c].z * kk.z + qv[c].w * kk.w;
            }
            // reduce over the 4 dim-chunk threads (lanes 4q..4q+3)
            p += __shfl_xor_sync(0xffffffffu, p, 1);
            p += __shfl_xor_sync(0xffffffffu, p, 2);
            if (kt == qt && (kt * 32 + kc) > qglob) p = -1e30f;
            sc[kc] = p;
            mt = fmaxf(mt, p);
        }

        float nm = fmaxf(mrun, mt);
        float corr = __expf(mrun - nm);
        l *= corr;
#pragma unroll
        for (int c = 0; c < 4; c++) {
            acc4[c].x *= corr; acc4[c].y *= corr; acc4[c].z *= corr; acc4[c].w *= corr;
        }
        float ps = 0.f;
#pragma unroll
        for (int kc = 0; kc < 32; kc++) {
            float p = __expf(sc[kc] - nm);
            ps += p;
            sc[kc] = p;
        }
        l += ps;
        mrun = nm;
#pragma unroll
        for (int kc = 0; kc < 32; kc++) {
            const float4* vr = (const float4*)&Vs[kc][cs * 16];
            float p = sc[kc];
#pragma unroll
            for (int c = 0; c < 4; c++) {
                float4 vv = vr[c];
                acc4[c].x += p * vv.x; acc4[c].y += p * vv.y;
                acc4[c].z += p * vv.z; acc4[c].w += p * vv.w;
            }
        }
    }

    float inv = 1.0f / l;
    float* op = out + (size_t)(b * SS + qglob) * DD + h * HDIM + cs * 16;
#pragma unroll
    for (int c = 0; c < 4; c++) {
        float4 o;
        o.x = acc4[c].x * inv; o.y = acc4[c].y * inv;
        o.z = acc4[c].z * inv; o.w = acc4[c].w * inv;
        *(float4*)(op + c * 4) = o;
    }
}

// ---------------- launch ---------------------------------------------------
extern "C" void kernel_launch(void* const* d_in, const int* in_sizes, int n_in,
                              void* d_out, int out_size)
{
    const float* x    = (const float*)d_in[0];
    const float* pos  = (const float*)d_in[1];
    const float* ln1g = (const float*)d_in[2];
    const float* ln1b = (const float*)d_in[3];
    const float* wqkv = (const float*)d_in[4];
    const float* bqkv = (const float*)d_in[5];
    const float* wo   = (const float*)d_in[6];
    const float* bo   = (const float*)d_in[7];
    const float* ln2g = (const float*)d_in[8];
    const float* ln2b = (const float*)d_in[9];
    const float* wfc  = (const float*)d_in[10];
    const float* bfc  = (const float*)d_in[11];
    const float* wpr  = (const float*)d_in[12];
    const float* bpr  = (const float*)d_in[13];
    float* out = (float*)d_out;

    float *p_h, *p_qkv, *p_attn, *p_x2, *p_m, *p_ff;
    cudaGetSymbolAddress((void**)&p_h,    g_h);
    cudaGetSymbolAddress((void**)&p_qkv,  g_qkv);
    cudaGetSymbolAddress((void**)&p_attn, g_attn);
    cudaGetSymbolAddress((void**)&p_x2,   g_x2);
    cudaGetSymbolAddress((void**)&p_m,    g_m);
    cudaGetSymbolAddress((void**)&p_ff,   g_ff);

    // 1) h = LN1(x) + pos
    ln_kernel<<<ROWS, 256>>>(x, ln1g, ln1b, pos, p_h);

    // 2) qkv = h @ w_qkv + b_qkv      [4096 x 3072]
    gemm_kernel<0><<<dim3(3 * DD / 128, ROWS / 128), 256>>>(
        p_h, wqkv, bqkv, nullptr, p_qkv, ROWS, 3 * DD, DD);

    // 3) causal attention -> [B,S,D]
    attn_kernel<<<dim3(SS / 32, HH, BB), 128>>>(p_qkv, p_attn);

    // 4) x2 = x + attn @ w_o + b_o    [4096 x 1024]
    gemm_kernel<2><<<dim3(DD / 128, ROWS / 128), 256>>>(
        p_attn, wo, bo, x, p_x2, ROWS, DD, DD);

    // 5) m = LN2(x2)
    ln_kernel<<<ROWS, 256>>>(p_x2, ln2g, ln2b, nullptr, p_m);

    // 6) ff = gelu(m @ w_fc + b_fc)   [4096 x 4096]
    gemm_kernel<1><<<dim3(DFFN / 128, ROWS / 128), 256>>>(
        p_m, wfc, bfc, nullptr, p_ff, ROWS, DFFN, DD);

    // 7) out = x2 + ff @ w_proj + b_proj  [4096 x 1024]
    gemm_kernel<2><<<dim3(DD / 128, ROWS / 128), 256>>>(
        p_ff, wpr, bpr, p_x2, out, ROWS, DD, DFFN);
}